// round 1
// baseline (speedup 1.0000x reference)
#include <cuda_runtime.h>
#include <cuda_bf16.h>

#define BB 8
#define NN 1024
#define NP (BB*NN)
#define KK 20

// ---------------- scratch (device globals; no allocation allowed) -------------
__device__ float g_h1[NP*256];
__device__ float g_h2[NP*256];
__device__ float g_dist[(size_t)BB*NN*NN];
__device__ int   g_idx[NP*KK];
__device__ float g_xx[NP];
__device__ float g_w1t[512*1024];   // transposed weights (also reused for Wf^T)
__device__ float g_wd[128*256];     // (W2 - W1) transposed, edge layers only
__device__ float g_fused[(size_t)NP*512];
__device__ float g_psum[(size_t)NP*256];
__device__ float g_pssq[(size_t)NP*256];
__device__ float g_scale[1024];
__device__ float g_shift[1024];

// ---------------- ||x||^2 per point ------------------------------------------
__global__ void xx_kernel(const float* __restrict__ h, int C) {
    int p = blockIdx.x;
    __shared__ float sh[64];
    float s = 0.f;
    for (int c = threadIdx.x; c < C; c += 64) {
        float v = h[(size_t)p*C + c];
        s += v*v;
    }
    sh[threadIdx.x] = s; __syncthreads();
    for (int st = 32; st > 0; st >>= 1) {
        if (threadIdx.x < st) sh[threadIdx.x] += sh[threadIdx.x + st];
        __syncthreads();
    }
    if (threadIdx.x == 0) g_xx[p] = sh[0];
}

// ---------------- neg_dist = 2<xn,xm> - xx_n - xx_m  (tiled GEMM) -------------
__global__ void __launch_bounds__(1024) negdist_kernel(const float* __restrict__ h, int C) {
    __shared__ float As[32][33];
    __shared__ float Bs[32][33];
    int b  = blockIdx.z;
    int n0 = blockIdx.y * 32, m0 = blockIdx.x * 32;
    int tx = threadIdx.x, ty = threadIdx.y;
    float acc = 0.f;
    for (int c0 = 0; c0 < C; c0 += 32) {
        int c = c0 + tx;
        As[ty][tx] = (c < C) ? h[((size_t)(b*NN) + (n0+ty))*C + c] : 0.f;
        Bs[ty][tx] = (c < C) ? h[((size_t)(b*NN) + (m0+ty))*C + c] : 0.f;
        __syncthreads();
        #pragma unroll
        for (int j = 0; j < 32; j++) acc += As[ty][j] * Bs[tx][j];
        __syncthreads();
    }
    int n = n0 + ty, m = m0 + tx;
    g_dist[((size_t)(b*NN) + n)*NN + m] = 2.f*acc - g_xx[b*NN + n] - g_xx[b*NN + m];
}

// ---------------- top-k (=20) by iterative block argmax -----------------------
__global__ void topk_kernel() {
    int p = blockIdx.x;
    __shared__ float d[NN];
    __shared__ float sv[256];
    __shared__ int   si[256];
    const float* row = g_dist + (size_t)p*NN;
    for (int m = threadIdx.x; m < NN; m += 256) d[m] = row[m];
    __syncthreads();
    for (int k = 0; k < KK; k++) {
        float bv = -1e30f; int bi = 0;
        for (int m = threadIdx.x; m < NN; m += 256) {
            float v = d[m];
            if (v > bv) { bv = v; bi = m; }
        }
        sv[threadIdx.x] = bv; si[threadIdx.x] = bi;
        __syncthreads();
        for (int st = 128; st > 0; st >>= 1) {
            if (threadIdx.x < st) {
                if (sv[threadIdx.x + st] > sv[threadIdx.x]) {
                    sv[threadIdx.x] = sv[threadIdx.x + st];
                    si[threadIdx.x] = si[threadIdx.x + st];
                }
            }
            __syncthreads();
        }
        if (threadIdx.x == 0) {
            g_idx[p*KK + k] = si[0];
            d[si[0]] = -1e30f;
        }
        __syncthreads();
    }
}

// ---------------- transpose edge weights: W(out,2C) -> W1t(C,out), Wd(C,out) --
__global__ void wtrans_kernel(const float* __restrict__ W, int C, int OUT) {
    int i = blockIdx.x*256 + threadIdx.x;
    if (i >= C*OUT) return;
    int c = i / OUT, o = i - c*OUT;
    float w1 = W[(size_t)o*2*C + c];
    float w2 = W[(size_t)o*2*C + C + c];
    g_w1t[(size_t)c*OUT + o] = w1;
    g_wd [(size_t)c*OUT + o] = w2 - w1;
}

// ---------------- edge conv: per-point block, max over k + stats --------------
// y_{k,o} = sum_c W1[o,c]*feat[k,c] + sum_c (W2-W1)[o,c]*ctr[c]
__global__ void edgeconv_kernel(const float* __restrict__ h, int C, int OUT, int foff) {
    extern __shared__ float sm[];
    float* ctr  = sm;          // C floats
    float* feat = sm + C;      // KK*C floats
    __shared__ int nb[KK];
    int p   = blockIdx.x;
    int tid = threadIdx.x;     // blockDim == OUT
    int b   = p / NN;
    if (tid < KK) nb[tid] = g_idx[p*KK + tid];
    for (int c = tid; c < C; c += OUT) ctr[c] = h[(size_t)p*C + c];
    __syncthreads();
    for (int t = tid; t < KK*C; t += OUT) {
        int k = t / C, c = t - k*C;
        feat[t] = h[((size_t)(b*NN) + nb[k])*C + c];
    }
    __syncthreads();

    int o = tid;
    float base = 0.f;
    for (int c = 0; c < C; c++) base += g_wd[(size_t)c*OUT + o] * ctr[c];
    float acc[KK];
    #pragma unroll
    for (int k = 0; k < KK; k++) acc[k] = base;

    if ((C & 3) == 0) {
        const float4* f4 = reinterpret_cast<const float4*>(feat);
        int C4 = C >> 2;
        for (int c4 = 0; c4 < C4; c4++) {
            int c = c4 * 4;
            float w0 = g_w1t[(size_t)(c+0)*OUT + o];
            float w1 = g_w1t[(size_t)(c+1)*OUT + o];
            float w2 = g_w1t[(size_t)(c+2)*OUT + o];
            float w3 = g_w1t[(size_t)(c+3)*OUT + o];
            #pragma unroll
            for (int k = 0; k < KK; k++) {
                float4 f = f4[k*C4 + c4];
                acc[k] += w0*f.x + w1*f.y + w2*f.z + w3*f.w;
            }
        }
    } else {
        for (int c = 0; c < C; c++) {
            float w = g_w1t[(size_t)c*OUT + o];
            #pragma unroll
            for (int k = 0; k < KK; k++) acc[k] += w * feat[k*C + c];
        }
    }

    float mx = -1e30f, s = 0.f, q = 0.f;
    #pragma unroll
    for (int k = 0; k < KK; k++) {
        mx = fmaxf(mx, acc[k]);
        s += acc[k];
        q += acc[k]*acc[k];
    }
    g_fused[(size_t)p*512 + foff + o] = mx;   // raw (pre-BN) max
    g_psum[(size_t)p*OUT + o] = s;
    g_pssq[(size_t)p*OUT + o] = q;
}

// ---------------- per-channel BN stats -> scale/shift (deterministic tree) ----
__global__ void chanstats_kernel(const float* __restrict__ g,
                                 const float* __restrict__ bta,
                                 int OUT, int P, float invM) {
    int o = blockIdx.x;
    __shared__ float ssum[256], ssq[256];
    float s = 0.f, q = 0.f;
    for (int p = threadIdx.x; p < P; p += 256) {
        s += g_psum[(size_t)p*OUT + o];
        q += g_pssq[(size_t)p*OUT + o];
    }
    ssum[threadIdx.x] = s; ssq[threadIdx.x] = q;
    __syncthreads();
    for (int st = 128; st > 0; st >>= 1) {
        if (threadIdx.x < st) {
            ssum[threadIdx.x] += ssum[threadIdx.x + st];
            ssq [threadIdx.x] += ssq [threadIdx.x + st];
        }
        __syncthreads();
    }
    if (threadIdx.x == 0) {
        float mean = ssum[0] * invM;
        float var  = ssq[0] * invM - mean*mean;
        float sc   = rsqrtf(var + 1e-5f) * g[o];
        g_scale[o] = sc;
        g_shift[o] = bta[o] - mean * sc;
    }
}

// ---------------- apply BN + LeakyReLU to maxed values; feed next layer -------
__global__ void normedge_kernel(int OUT, int foff, float* __restrict__ hnext) {
    int i = blockIdx.x*256 + threadIdx.x;
    if (i >= NP*OUT) return;
    int p = i / OUT, o = i - p*OUT;
    float v = g_fused[(size_t)p*512 + foff + o] * g_scale[o] + g_shift[o];
    v = v > 0.f ? v : 0.2f*v;
    g_fused[(size_t)p*512 + foff + o] = v;
    hnext[i] = v;
}

// ---------------- transpose Wf (1024,512) -> (512,1024) -----------------------
__global__ void wftrans_kernel(const float* __restrict__ Wf) {
    int i = blockIdx.x*256 + threadIdx.x;
    if (i >= 512*1024) return;
    int c = i >> 10, o = i & 1023;
    g_w1t[(size_t)c*1024 + o] = Wf[(size_t)o*512 + c];
}

// ---------------- final linear: 8-point tile per block + stats ----------------
#define TP 8
__global__ void __launch_bounds__(1024) final_kernel(float* __restrict__ out) {
    __shared__ float f[TP*512];
    int pb  = blockIdx.x;      // point tile
    int tid = threadIdx.x;     // 1024 = one output channel each
    for (int t = tid; t < TP*512; t += 1024) {
        int p = t >> 9, c = t & 511;
        f[t] = g_fused[(size_t)(pb*TP + p)*512 + c];
    }
    __syncthreads();
    int o = tid;
    float acc[TP];
    #pragma unroll
    for (int p = 0; p < TP; p++) acc[p] = 0.f;
    const float4* f4 = reinterpret_cast<const float4*>(f);
    for (int c4 = 0; c4 < 128; c4++) {
        int c = c4 * 4;
        float w0 = g_w1t[(size_t)(c+0)*1024 + o];
        float w1 = g_w1t[(size_t)(c+1)*1024 + o];
        float w2 = g_w1t[(size_t)(c+2)*1024 + o];
        float w3 = g_w1t[(size_t)(c+3)*1024 + o];
        #pragma unroll
        for (int p = 0; p < TP; p++) {
            float4 fv = f4[p*128 + c4];
            acc[p] += w0*fv.x + w1*fv.y + w2*fv.z + w3*fv.w;
        }
    }
    float s = 0.f, q = 0.f;
    #pragma unroll
    for (int p = 0; p < TP; p++) {
        s += acc[p]; q += acc[p]*acc[p];
        out[(size_t)(pb*TP + p)*1024 + o] = acc[p];   // raw y
    }
    g_psum[(size_t)pb*1024 + o] = s;
    g_pssq[(size_t)pb*1024 + o] = q;
}

// ---------------- final BN + LeakyReLU in place --------------------------------
__global__ void normout_kernel(float* __restrict__ out) {
    int i = blockIdx.x*256 + threadIdx.x;
    if (i >= NP*1024) return;
    int o = i & 1023;
    float v = out[i] * g_scale[o] + g_shift[o];
    out[i] = v > 0.f ? v : 0.2f*v;
}

// ------------------------------- launcher -------------------------------------
extern "C" void kernel_launch(void* const* d_in, const int* in_sizes, int n_in,
                              void* d_out, int out_size) {
    (void)in_sizes; (void)n_in; (void)out_size;
    const float* x  = (const float*)d_in[0];
    const float* W[4]  = {(const float*)d_in[1],  (const float*)d_in[4],
                          (const float*)d_in[7],  (const float*)d_in[10]};
    const float* ga[4] = {(const float*)d_in[2],  (const float*)d_in[5],
                          (const float*)d_in[8],  (const float*)d_in[11]};
    const float* bt[4] = {(const float*)d_in[3],  (const float*)d_in[6],
                          (const float*)d_in[9],  (const float*)d_in[12]};
    const float* Wf = (const float*)d_in[13];
    const float* gf = (const float*)d_in[14];
    const float* bf = (const float*)d_in[15];
    float* out = (float*)d_out;

    float *h1, *h2;
    cudaGetSymbolAddress((void**)&h1, g_h1);
    cudaGetSymbolAddress((void**)&h2, g_h2);
    float* hn[2] = {h1, h2};

    const int Cs[4]    = {3, 64, 64, 128};
    const int OUTs[4]  = {64, 64, 128, 256};
    const int foffs[4] = {0, 64, 128, 256};

    const float* hcur = x;
    for (int i = 0; i < 4; i++) {
        int C = Cs[i], OUT = OUTs[i];
        xx_kernel<<<NP, 64>>>(hcur, C);
        negdist_kernel<<<dim3(NN/32, NN/32, BB), dim3(32, 32)>>>(hcur, C);
        topk_kernel<<<NP, 256>>>();
        wtrans_kernel<<<(C*OUT + 255)/256, 256>>>(W[i], C, OUT);
        size_t smem = (size_t)(C + KK*C) * sizeof(float);
        edgeconv_kernel<<<NP, OUT, smem>>>(hcur, C, OUT, foffs[i]);
        chanstats_kernel<<<OUT, 256>>>(ga[i], bt[i], OUT, NP, 1.f/((float)NP*KK));
        normedge_kernel<<<(NP*OUT + 255)/256, 256>>>(OUT, foffs[i], hn[i & 1]);
        hcur = hn[i & 1];
    }

    wftrans_kernel<<<(512*1024 + 255)/256, 256>>>(Wf);
    final_kernel<<<NP/TP, 1024>>>(out);
    chanstats_kernel<<<1024, 256>>>(gf, bf, 1024, NP/TP, 1.f/(float)NP);
    normout_kernel<<<(NP*1024 + 255)/256, 256>>>(out);
}

// round 2
// speedup vs baseline: 1.6441x; 1.6441x over previous
#include <cuda_runtime.h>
#include <cuda_bf16.h>

#define BB 8
#define NN 1024
#define NP (BB*NN)
#define KK 20

// ---------------- scratch (device globals; no allocation allowed) -------------
__device__ float g_h1[NP*256];
__device__ float g_h2[NP*256];
__device__ float g_dist[(size_t)BB*NN*NN];
__device__ int   g_idx[NP*KK];
__device__ float g_xx[NP];
__device__ ulonglong2 g_w1p[131072];         // packed weights [c4*OUT + o] (pairs)
__device__ float4     g_wdp[8192];           // packed (W2-W1) [c4*OUT + o]
__device__ float g_fused[(size_t)NP*512];
__device__ float g_psum[(size_t)NP*256];     // transposed: [o*P + p]
__device__ float g_pssq[(size_t)NP*256];
__device__ float g_scale[1024];
__device__ float g_shift[1024];

__device__ __forceinline__ void fma2(unsigned long long& d,
                                     unsigned long long a, unsigned long long b) {
    asm("fma.rn.f32x2 %0, %1, %2, %0;" : "+l"(d) : "l"(a), "l"(b));
}
__device__ __forceinline__ unsigned long long pack2(float lo, float hi) {
    unsigned long long r;
    asm("mov.b64 %0, {%1, %2};" : "=l"(r) : "f"(lo), "f"(hi));
    return r;
}
__device__ __forceinline__ void unpack2(float& lo, float& hi, unsigned long long v) {
    asm("mov.b64 {%0, %1}, %2;" : "=f"(lo), "=f"(hi) : "l"(v));
}

// ---------------- ||x||^2 per point ------------------------------------------
__global__ void xx_kernel(const float* __restrict__ h, int C) {
    int p = blockIdx.x;
    __shared__ float sh[64];
    float s = 0.f;
    for (int c = threadIdx.x; c < C; c += 64) {
        float v = h[(size_t)p*C + c];
        s += v*v;
    }
    sh[threadIdx.x] = s; __syncthreads();
    for (int st = 32; st > 0; st >>= 1) {
        if (threadIdx.x < st) sh[threadIdx.x] += sh[threadIdx.x + st];
        __syncthreads();
    }
    if (threadIdx.x == 0) g_xx[p] = sh[0];
}

// ---------------- neg_dist: 64x64 register-tiled GEMM + f32x2 ------------------
__global__ void __launch_bounds__(256) negdist_kernel(const float* __restrict__ h, int C) {
    __shared__ float As[16][68];
    __shared__ float Bs[16][68];
    int b  = blockIdx.z;
    int n0 = blockIdx.y * 64, m0 = blockIdx.x * 64;
    int tid = threadIdx.x;
    int tx = tid & 15, ty = tid >> 4;
    unsigned long long acc[4][2];
    #pragma unroll
    for (int i = 0; i < 4; i++) { acc[i][0] = 0ull; acc[i][1] = 0ull; }

    for (int c0 = 0; c0 < C; c0 += 16) {
        #pragma unroll
        for (int r = 0; r < 4; r++) {
            int idx = tid + r*256;
            int cc = idx & 15, n = idx >> 4;
            int c = c0 + cc;
            As[cc][n] = (c < C) ? h[((size_t)(b*NN) + n0 + n)*C + c] : 0.f;
            Bs[cc][n] = (c < C) ? h[((size_t)(b*NN) + m0 + n)*C + c] : 0.f;
        }
        __syncthreads();
        #pragma unroll
        for (int kk = 0; kk < 16; kk++) {
            float4 a = *(const float4*)&As[kk][ty*4];
            ulonglong2 bb = *(const ulonglong2*)&Bs[kk][tx*4];
            unsigned long long a0 = pack2(a.x, a.x);
            unsigned long long a1 = pack2(a.y, a.y);
            unsigned long long a2 = pack2(a.z, a.z);
            unsigned long long a3 = pack2(a.w, a.w);
            fma2(acc[0][0], a0, bb.x); fma2(acc[0][1], a0, bb.y);
            fma2(acc[1][0], a1, bb.x); fma2(acc[1][1], a1, bb.y);
            fma2(acc[2][0], a2, bb.x); fma2(acc[2][1], a2, bb.y);
            fma2(acc[3][0], a3, bb.x); fma2(acc[3][1], a3, bb.y);
        }
        __syncthreads();
    }
    #pragma unroll
    for (int i = 0; i < 4; i++) {
        int n = n0 + ty*4 + i;
        float xn = g_xx[b*NN + n];
        #pragma unroll
        for (int jp = 0; jp < 2; jp++) {
            float lo, hi;
            unpack2(lo, hi, acc[i][jp]);
            int m = m0 + tx*4 + jp*2;
            g_dist[((size_t)(b*NN) + n)*NN + m]     = 2.f*lo - xn - g_xx[b*NN + m];
            g_dist[((size_t)(b*NN) + n)*NN + m + 1] = 2.f*hi - xn - g_xx[b*NN + m + 1];
        }
    }
}

// ---------------- top-k: warp per point, register-resident --------------------
__global__ void topk_kernel() {
    int lane = threadIdx.x & 31;
    int p = blockIdx.x * 8 + (threadIdx.x >> 5);
    const float* row = g_dist + (size_t)p*NN;
    float v[32];
    #pragma unroll
    for (int j = 0; j < 32; j++) v[j] = row[j*32 + lane];
    float lm = -1e30f; int ls = 0;
    #pragma unroll
    for (int j = 0; j < 32; j++) {
        if (v[j] > lm) { lm = v[j]; ls = j; }
    }
    for (int k = 0; k < KK; k++) {
        float bv = lm; int gi = ls*32 + lane;
        #pragma unroll
        for (int off = 16; off > 0; off >>= 1) {
            float ov = __shfl_xor_sync(0xffffffffu, bv, off);
            int   og = __shfl_xor_sync(0xffffffffu, gi, off);
            if (ov > bv || (ov == bv && og < gi)) { bv = ov; gi = og; }
        }
        if (lane == 0) g_idx[p*KK + k] = gi;
        if (lane == (gi & 31)) {
            int bs = gi >> 5;
            float nm = -1e30f; int ns = 0;
            #pragma unroll
            for (int j = 0; j < 32; j++) {
                if (j == bs) v[j] = -1e30f;
                if (v[j] > nm) { nm = v[j]; ns = j; }
            }
            lm = nm; ls = ns;
        }
        lm = __shfl_sync(0xffffffffu, lm, lane);  // no-op, keeps convergence explicit
    }
}

// ---------------- weight transform: W(out,2C) -> packed pairs -----------------
__global__ void wtrans_kernel(const float* __restrict__ W, int C, int Cp, int OUT) {
    int i = blockIdx.x*256 + threadIdx.x;
    int total = (Cp >> 2) * OUT;
    if (i >= total) return;
    int o = i % OUT;
    int c4 = i / OUT;
    float w1[4], wd[4];
    #pragma unroll
    for (int j = 0; j < 4; j++) {
        int c = c4*4 + j;
        if (c < C) {
            float a = W[(size_t)o*2*C + c];
            float b2 = W[(size_t)o*2*C + C + c];
            w1[j] = a; wd[j] = b2 - a;
        } else { w1[j] = 0.f; wd[j] = 0.f; }
    }
    ulonglong2 wp;
    wp.x = pack2(w1[0], w1[1]);
    wp.y = pack2(w1[2], w1[3]);
    g_w1p[i] = wp;
    g_wdp[i] = make_float4(wd[0], wd[1], wd[2], wd[3]);
}

// ---------------- edge conv: per-point block, f32x2, max over k + stats -------
__global__ void edgeconv_kernel(const float* __restrict__ h, int C, int Cp,
                                int lc, int OUT, int foff) {
    extern __shared__ float sm[];
    float* ctr  = sm;          // Cp floats
    float* feat = sm + Cp;     // KK*Cp floats
    __shared__ int nb[32];
    int p   = blockIdx.x;
    int tid = threadIdx.x;     // blockDim == OUT
    int b   = p >> 10;
    if (tid < KK) nb[tid] = g_idx[p*KK + tid];
    for (int c = tid; c < Cp; c += OUT)
        ctr[c] = (c < C) ? h[(size_t)p*C + c] : 0.f;
    __syncthreads();
    int mask = Cp - 1;
    for (int t = tid; t < KK*Cp; t += OUT) {
        int k = t >> lc, c = t & mask;
        feat[t] = (c < C) ? h[((size_t)(b << 10) + nb[k])*C + c] : 0.f;
    }
    __syncthreads();

    int o = tid;
    int C4 = Cp >> 2;
    float base = 0.f;
    const float4* c4p = (const float4*)ctr;
    for (int c4 = 0; c4 < C4; c4++) {
        float4 w = g_wdp[c4*OUT + o];
        float4 cv = c4p[c4];
        base += w.x*cv.x + w.y*cv.y + w.z*cv.z + w.w*cv.w;
    }
    unsigned long long acc[KK];
    #pragma unroll
    for (int k = 0; k < KK; k++) acc[k] = 0ull;

    const ulonglong2* f2 = (const ulonglong2*)feat;
    for (int c4 = 0; c4 < C4; c4++) {
        ulonglong2 wv = g_w1p[c4*OUT + o];
        #pragma unroll
        for (int k = 0; k < KK; k++) {
            ulonglong2 fv = f2[k*C4 + c4];
            fma2(acc[k], wv.x, fv.x);
            fma2(acc[k], wv.y, fv.y);
        }
    }

    float mx = -1e30f, s = 0.f, q = 0.f;
    #pragma unroll
    for (int k = 0; k < KK; k++) {
        float lo, hi;
        unpack2(lo, hi, acc[k]);
        float y = base + lo + hi;
        mx = fmaxf(mx, y);
        s += y;
        q += y*y;
    }
    g_fused[(size_t)p*512 + foff + o] = mx;   // raw (pre-BN) max
    g_psum[(size_t)o*NP + p] = s;
    g_pssq[(size_t)o*NP + p] = q;
}

// ---------------- per-channel BN stats (coalesced, deterministic) -------------
__global__ void chanstats_kernel(const float* __restrict__ g,
                                 const float* __restrict__ bta,
                                 int P, float invM) {
    int o = blockIdx.x;
    __shared__ float ssum[256], ssq[256];
    const float* ps = g_psum + (size_t)o*P;
    const float* pq = g_pssq + (size_t)o*P;
    float s = 0.f, q = 0.f;
    for (int i = threadIdx.x; i < P; i += 256) { s += ps[i]; q += pq[i]; }
    ssum[threadIdx.x] = s; ssq[threadIdx.x] = q;
    __syncthreads();
    for (int st = 128; st > 0; st >>= 1) {
        if (threadIdx.x < st) {
            ssum[threadIdx.x] += ssum[threadIdx.x + st];
            ssq [threadIdx.x] += ssq [threadIdx.x + st];
        }
        __syncthreads();
    }
    if (threadIdx.x == 0) {
        float mean = ssum[0] * invM;
        float var  = ssq[0] * invM - mean*mean;
        float sc   = rsqrtf(var + 1e-5f) * g[o];
        g_scale[o] = sc;
        g_shift[o] = bta[o] - mean * sc;
    }
}

// ---------------- apply BN + LeakyReLU to maxed values; feed next layer -------
__global__ void normedge_kernel(int OUT, int foff, float* __restrict__ hnext) {
    int i = blockIdx.x*256 + threadIdx.x;
    if (i >= NP*OUT) return;
    int p = i / OUT, o = i - p*OUT;
    float v = g_fused[(size_t)p*512 + foff + o] * g_scale[o] + g_shift[o];
    v = v > 0.f ? v : 0.2f*v;
    g_fused[(size_t)p*512 + foff + o] = v;
    hnext[i] = v;
}

// ---------------- transpose Wf (1024,512) -> packed pairs ---------------------
__global__ void wftrans_kernel(const float* __restrict__ Wf) {
    int i = blockIdx.x*256 + threadIdx.x;
    if (i >= 128*1024) return;
    int o = i & 1023;
    int c4 = i >> 10;
    float w0 = Wf[(size_t)o*512 + c4*4 + 0];
    float w1 = Wf[(size_t)o*512 + c4*4 + 1];
    float w2 = Wf[(size_t)o*512 + c4*4 + 2];
    float w3 = Wf[(size_t)o*512 + c4*4 + 3];
    ulonglong2 wp;
    wp.x = pack2(w0, w1);
    wp.y = pack2(w2, w3);
    g_w1p[(size_t)c4*1024 + o] = wp;
}

// ---------------- final linear: 16-point tile, f32x2 --------------------------
#define TP 16
__global__ void __launch_bounds__(1024) final_kernel(float* __restrict__ out) {
    __shared__ float f[TP*512];
    int pb  = blockIdx.x;
    int tid = threadIdx.x;
    for (int t = tid; t < TP*512; t += 1024)
        f[t] = g_fused[(size_t)(pb*TP + (t >> 9))*512 + (t & 511)];
    __syncthreads();
    int o = tid;
    unsigned long long acc[TP];
    #pragma unroll
    for (int p = 0; p < TP; p++) acc[p] = 0ull;
    const ulonglong2* f2 = (const ulonglong2*)f;
    for (int c4 = 0; c4 < 128; c4++) {
        ulonglong2 wv = g_w1p[(size_t)c4*1024 + o];
        #pragma unroll
        for (int p = 0; p < TP; p++) {
            ulonglong2 fv = f2[p*128 + c4];
            fma2(acc[p], wv.x, fv.x);
            fma2(acc[p], wv.y, fv.y);
        }
    }
    float s = 0.f, q = 0.f;
    #pragma unroll
    for (int p = 0; p < TP; p++) {
        float lo, hi;
        unpack2(lo, hi, acc[p]);
        float y = lo + hi;
        out[(size_t)(pb*TP + p)*1024 + o] = y;   // raw y
        s += y; q += y*y;
    }
    g_psum[(size_t)o*(NP/TP) + pb] = s;
    g_pssq[(size_t)o*(NP/TP) + pb] = q;
}

// ---------------- final BN + LeakyReLU in place --------------------------------
__global__ void normout_kernel(float* __restrict__ out) {
    int i = blockIdx.x*256 + threadIdx.x;
    if (i >= NP*1024) return;
    int o = i & 1023;
    float v = out[i] * g_scale[o] + g_shift[o];
    out[i] = v > 0.f ? v : 0.2f*v;
}

// ------------------------------- launcher -------------------------------------
extern "C" void kernel_launch(void* const* d_in, const int* in_sizes, int n_in,
                              void* d_out, int out_size) {
    (void)in_sizes; (void)n_in; (void)out_size;
    const float* x  = (const float*)d_in[0];
    const float* W[4]  = {(const float*)d_in[1],  (const float*)d_in[4],
                          (const float*)d_in[7],  (const float*)d_in[10]};
    const float* ga[4] = {(const float*)d_in[2],  (const float*)d_in[5],
                          (const float*)d_in[8],  (const float*)d_in[11]};
    const float* bt[4] = {(const float*)d_in[3],  (const float*)d_in[6],
                          (const float*)d_in[9],  (const float*)d_in[12]};
    const float* Wf = (const float*)d_in[13];
    const float* gf = (const float*)d_in[14];
    const float* bf = (const float*)d_in[15];
    float* out = (float*)d_out;

    float *h1, *h2;
    cudaGetSymbolAddress((void**)&h1, g_h1);
    cudaGetSymbolAddress((void**)&h2, g_h2);
    float* hn[2] = {h1, h2};

    const int Cs[4]    = {3, 64, 64, 128};
    const int Cps[4]   = {4, 64, 64, 128};
    const int lcs[4]   = {2, 6, 6, 7};
    const int OUTs[4]  = {64, 64, 128, 256};
    const int foffs[4] = {0, 64, 128, 256};

    const float* hcur = x;
    for (int i = 0; i < 4; i++) {
        int C = Cs[i], Cp = Cps[i], OUT = OUTs[i];
        xx_kernel<<<NP, 64>>>(hcur, C);
        negdist_kernel<<<dim3(NN/64, NN/64, BB), 256>>>(hcur, C);
        topk_kernel<<<NP/8, 256>>>();
        int wtot = (Cp/4)*OUT;
        wtrans_kernel<<<(wtot + 255)/256, 256>>>(W[i], C, Cp, OUT);
        size_t smem = (size_t)(Cp + KK*Cp) * sizeof(float);
        edgeconv_kernel<<<NP, OUT, smem>>>(hcur, C, Cp, lcs[i], OUT, foffs[i]);
        chanstats_kernel<<<OUT, 256>>>(ga[i], bt[i], NP, 1.f/((float)NP*KK));
        normedge_kernel<<<(NP*OUT + 255)/256, 256>>>(OUT, foffs[i], hn[i & 1]);
        hcur = hn[i & 1];
    }

    wftrans_kernel<<<(128*1024 + 255)/256, 256>>>(Wf);
    final_kernel<<<NP/TP, 1024>>>(out);
    chanstats_kernel<<<1024, 256>>>(gf, bf, NP/TP, 1.f/(float)NP);
    normout_kernel<<<(NP*1024 + 255)/256, 256>>>(out);
}

// round 3
// speedup vs baseline: 1.8059x; 1.0984x over previous
#include <cuda_runtime.h>
#include <cuda_bf16.h>

#define BB 8
#define NN 1024
#define NP (BB*NN)
#define KK 20

// ---------------- scratch (device globals; no allocation allowed) -------------
__device__ float g_h1[NP*256];
__device__ float g_h2[NP*256];
__device__ float g_dist[(size_t)BB*NN*NN];
__device__ int   g_idx[NP*KK];
__device__ float g_xx[NP];
__device__ ulonglong2 g_w1p[131072];         // packed weights (also Wf packed)
__device__ float4     g_wdp[8192];           // packed (W2-W1)
__device__ float g_fused[(size_t)NP*512];
__device__ float g_psum[(size_t)NP*256];     // transposed: [o*P + p]
__device__ float g_pssq[(size_t)NP*256];
__device__ float g_scale[1024];
__device__ float g_shift[1024];

__device__ __forceinline__ void fma2(unsigned long long& d,
                                     unsigned long long a, unsigned long long b) {
    asm("fma.rn.f32x2 %0, %1, %2, %0;" : "+l"(d) : "l"(a), "l"(b));
}
__device__ __forceinline__ unsigned long long pack2(float lo, float hi) {
    unsigned long long r;
    asm("mov.b64 %0, {%1, %2};" : "=l"(r) : "f"(lo), "f"(hi));
    return r;
}
__device__ __forceinline__ void unpack2(float& lo, float& hi, unsigned long long v) {
    asm("mov.b64 {%0, %1}, %2;" : "=f"(lo), "=f"(hi) : "l"(v));
}

// ---------------- ||x||^2 per point (input layer only) -------------------------
__global__ void xx_kernel(const float* __restrict__ h, int C) {
    int p = blockIdx.x;
    __shared__ float sh[64];
    float s = 0.f;
    for (int c = threadIdx.x; c < C; c += 64) {
        float v = h[(size_t)p*C + c];
        s += v*v;
    }
    sh[threadIdx.x] = s; __syncthreads();
    for (int st = 32; st > 0; st >>= 1) {
        if (threadIdx.x < st) sh[threadIdx.x] += sh[threadIdx.x + st];
        __syncthreads();
    }
    if (threadIdx.x == 0) g_xx[p] = sh[0];
}

// ---------------- neg_dist: 64x64 register-tiled GEMM + f32x2 ------------------
__global__ void __launch_bounds__(256) negdist_kernel(const float* __restrict__ h, int C) {
    __shared__ float As[16][68];
    __shared__ float Bs[16][68];
    int b  = blockIdx.z;
    int n0 = blockIdx.y * 64, m0 = blockIdx.x * 64;
    int tid = threadIdx.x;
    int tx = tid & 15, ty = tid >> 4;
    unsigned long long acc[4][2];
    #pragma unroll
    for (int i = 0; i < 4; i++) { acc[i][0] = 0ull; acc[i][1] = 0ull; }

    for (int c0 = 0; c0 < C; c0 += 16) {
        #pragma unroll
        for (int r = 0; r < 4; r++) {
            int idx = tid + r*256;
            int cc = idx & 15, n = idx >> 4;
            int c = c0 + cc;
            As[cc][n] = (c < C) ? h[((size_t)(b*NN) + n0 + n)*C + c] : 0.f;
            Bs[cc][n] = (c < C) ? h[((size_t)(b*NN) + m0 + n)*C + c] : 0.f;
        }
        __syncthreads();
        #pragma unroll
        for (int kk = 0; kk < 16; kk++) {
            float4 a = *(const float4*)&As[kk][ty*4];
            ulonglong2 bb = *(const ulonglong2*)&Bs[kk][tx*4];
            unsigned long long a0 = pack2(a.x, a.x);
            unsigned long long a1 = pack2(a.y, a.y);
            unsigned long long a2 = pack2(a.z, a.z);
            unsigned long long a3 = pack2(a.w, a.w);
            fma2(acc[0][0], a0, bb.x); fma2(acc[0][1], a0, bb.y);
            fma2(acc[1][0], a1, bb.x); fma2(acc[1][1], a1, bb.y);
            fma2(acc[2][0], a2, bb.x); fma2(acc[2][1], a2, bb.y);
            fma2(acc[3][0], a3, bb.x); fma2(acc[3][1], a3, bb.y);
        }
        __syncthreads();
    }
    #pragma unroll
    for (int i = 0; i < 4; i++) {
        int n = n0 + ty*4 + i;
        float xn = g_xx[b*NN + n];
        #pragma unroll
        for (int jp = 0; jp < 2; jp++) {
            float lo, hi;
            unpack2(lo, hi, acc[i][jp]);
            int m = m0 + tx*4 + jp*2;
            g_dist[((size_t)(b*NN) + n)*NN + m]     = 2.f*lo - xn - g_xx[b*NN + m];
            g_dist[((size_t)(b*NN) + n)*NN + m + 1] = 2.f*hi - xn - g_xx[b*NN + m + 1];
        }
    }
}

// ---------------- top-k: warp per point, register-resident --------------------
__global__ void topk_kernel() {
    int lane = threadIdx.x & 31;
    int p = blockIdx.x * 8 + (threadIdx.x >> 5);
    const float* row = g_dist + (size_t)p*NN;
    float v[32];
    #pragma unroll
    for (int j = 0; j < 32; j++) v[j] = row[j*32 + lane];
    float lm = -1e30f; int ls = 0;
    #pragma unroll
    for (int j = 0; j < 32; j++) {
        if (v[j] > lm) { lm = v[j]; ls = j; }
    }
    for (int k = 0; k < KK; k++) {
        float bv = lm; int gi = ls*32 + lane;
        #pragma unroll
        for (int off = 16; off > 0; off >>= 1) {
            float ov = __shfl_xor_sync(0xffffffffu, bv, off);
            int   og = __shfl_xor_sync(0xffffffffu, gi, off);
            if (ov > bv || (ov == bv && og < gi)) { bv = ov; gi = og; }
        }
        if (lane == 0) g_idx[p*KK + k] = gi;
        if (lane == (gi & 31)) {
            int bs = gi >> 5;
            float nm = -1e30f; int ns = 0;
            #pragma unroll
            for (int j = 0; j < 32; j++) {
                if (j == bs) v[j] = -1e30f;
                if (v[j] > nm) { nm = v[j]; ns = j; }
            }
            lm = nm; ls = ns;
        }
    }
}

// ---------------- weight transform: W(out,2C) -> packed pairs -----------------
__global__ void wtrans_kernel(const float* __restrict__ W, int C, int Cp, int OUT) {
    int i = blockIdx.x*256 + threadIdx.x;
    int total = (Cp >> 2) * OUT;
    if (i >= total) return;
    int o = i % OUT;
    int c4 = i / OUT;
    float w1[4], wd[4];
    #pragma unroll
    for (int j = 0; j < 4; j++) {
        int c = c4*4 + j;
        if (c < C) {
            float a = W[(size_t)o*2*C + c];
            float b2 = W[(size_t)o*2*C + C + c];
            w1[j] = a; wd[j] = b2 - a;
        } else { w1[j] = 0.f; wd[j] = 0.f; }
    }
    ulonglong2 wp;
    wp.x = pack2(w1[0], w1[1]);
    wp.y = pack2(w1[2], w1[3]);
    g_w1p[i] = wp;
    g_wdp[i] = make_float4(wd[0], wd[1], wd[2], wd[3]);
}

// ---------------- edge conv: 2 outputs/thread, k-chunked, f32x2 ----------------
__global__ void edgeconv_kernel(const float* __restrict__ h, int C, int Cp,
                                int lc, int OUT, int foff) {
    extern __shared__ float sm[];
    float* ctr  = sm;          // Cp floats
    float* feat = sm + Cp;     // KK*Cp floats
    __shared__ int nb[32];
    int p   = blockIdx.x;
    int tid = threadIdx.x;
    int HALF = blockDim.x;     // OUT/2
    int b   = p >> 10;
    if (tid < KK) nb[tid] = g_idx[p*KK + tid];
    for (int c = tid; c < Cp; c += HALF)
        ctr[c] = (c < C) ? h[(size_t)p*C + c] : 0.f;
    __syncthreads();
    int mask = Cp - 1;
    for (int t = tid; t < KK*Cp; t += HALF) {
        int k = t >> lc, c = t & mask;
        feat[t] = (c < C) ? h[((size_t)((b << 10) + nb[k]))*C + c] : 0.f;
    }
    __syncthreads();

    int o0 = tid, o1 = tid + HALF;
    int C4 = Cp >> 2;
    const float4* c4p = (const float4*)ctr;
    float base0 = 0.f, base1 = 0.f;
    for (int c4 = 0; c4 < C4; c4++) {
        float4 cv = c4p[c4];
        float4 w0 = g_wdp[c4*OUT + o0];
        float4 w1 = g_wdp[c4*OUT + o1];
        base0 += w0.x*cv.x + w0.y*cv.y + w0.z*cv.z + w0.w*cv.w;
        base1 += w1.x*cv.x + w1.y*cv.y + w1.z*cv.z + w1.w*cv.w;
    }
    const ulonglong2* f2 = (const ulonglong2*)feat;
    float mx0=-1e30f, s0=0.f, q0=0.f;
    float mx1=-1e30f, s1=0.f, q1=0.f;
    #pragma unroll
    for (int kc = 0; kc < KK; kc += 10) {
        unsigned long long a0[10], a1[10];
        #pragma unroll
        for (int k = 0; k < 10; k++) { a0[k] = 0ull; a1[k] = 0ull; }
        for (int c4 = 0; c4 < C4; c4++) {
            ulonglong2 w0 = g_w1p[c4*OUT + o0];
            ulonglong2 w1 = g_w1p[c4*OUT + o1];
            #pragma unroll
            for (int k = 0; k < 10; k++) {
                ulonglong2 fv = f2[(kc+k)*C4 + c4];
                fma2(a0[k], w0.x, fv.x); fma2(a0[k], w0.y, fv.y);
                fma2(a1[k], w1.x, fv.x); fma2(a1[k], w1.y, fv.y);
            }
        }
        #pragma unroll
        for (int k = 0; k < 10; k++) {
            float lo, hi;
            unpack2(lo, hi, a0[k]);
            float y = base0 + lo + hi;
            mx0 = fmaxf(mx0, y); s0 += y; q0 += y*y;
            unpack2(lo, hi, a1[k]);
            y = base1 + lo + hi;
            mx1 = fmaxf(mx1, y); s1 += y; q1 += y*y;
        }
    }
    g_fused[(size_t)p*512 + foff + o0] = mx0;
    g_fused[(size_t)p*512 + foff + o1] = mx1;
    g_psum[(size_t)o0*NP + p] = s0; g_pssq[(size_t)o0*NP + p] = q0;
    g_psum[(size_t)o1*NP + p] = s1; g_pssq[(size_t)o1*NP + p] = q1;
}

// ---------------- per-channel BN stats (coalesced, deterministic) -------------
__global__ void chanstats_kernel(const float* __restrict__ g,
                                 const float* __restrict__ bta,
                                 int P, float invM) {
    int o = blockIdx.x;
    __shared__ float ssum[256], ssq[256];
    const float* ps = g_psum + (size_t)o*P;
    const float* pq = g_pssq + (size_t)o*P;
    float s = 0.f, q = 0.f;
    for (int i = threadIdx.x; i < P; i += 256) { s += ps[i]; q += pq[i]; }
    ssum[threadIdx.x] = s; ssq[threadIdx.x] = q;
    __syncthreads();
    for (int st = 128; st > 0; st >>= 1) {
        if (threadIdx.x < st) {
            ssum[threadIdx.x] += ssum[threadIdx.x + st];
            ssq [threadIdx.x] += ssq [threadIdx.x + st];
        }
        __syncthreads();
    }
    if (threadIdx.x == 0) {
        float mean = ssum[0] * invM;
        float var  = ssq[0] * invM - mean*mean;
        float sc   = rsqrtf(var + 1e-5f) * g[o];
        g_scale[o] = sc;
        g_shift[o] = bta[o] - mean * sc;
    }
}

// ---------------- BN + LeakyReLU on maxed values; also emits next ||h||^2 -----
__global__ void normedge_kernel(int OUT, int foff, float* __restrict__ hnext,
                                int wantxx) {
    __shared__ float sh[256];
    int p = blockIdx.x, o = threadIdx.x;
    float v = g_fused[(size_t)p*512 + foff + o] * g_scale[o] + g_shift[o];
    v = v > 0.f ? v : 0.2f*v;
    g_fused[(size_t)p*512 + foff + o] = v;
    hnext[(size_t)p*OUT + o] = v;
    sh[o] = v*v;
    __syncthreads();
    for (int st = OUT >> 1; st > 0; st >>= 1) {
        if (o < st) sh[o] += sh[o + st];
        __syncthreads();
    }
    if (o == 0 && wantxx) g_xx[p] = sh[0];
}

// ---------------- Wf (1024,512) -> packed output-pairs fw[c*512 + op] ---------
__global__ void wftrans_kernel(const float* __restrict__ Wf) {
    int i = blockIdx.x*256 + threadIdx.x;
    if (i >= 262144) return;
    int c = i >> 9, op = i & 511;
    unsigned long long v = pack2(Wf[(size_t)(2*op)*512 + c],
                                 Wf[(size_t)(2*op+1)*512 + c]);
    ((unsigned long long*)g_w1p)[i] = v;
}

// ---------------- final linear: 128x128x32 register-tiled GEMM ----------------
__global__ void __launch_bounds__(256) final_kernel(float* __restrict__ out) {
    __shared__ float fs[32][132];
    __shared__ float sred[2][16][128];
    int pb = blockIdx.x, ob = blockIdx.y;
    int tid = threadIdx.x;
    int tx = tid & 15, ty = tid >> 4;
    int pbase = pb * 128;
    unsigned long long acc[8][4];
    #pragma unroll
    for (int i = 0; i < 8; i++)
        #pragma unroll
        for (int j = 0; j < 4; j++) acc[i][j] = 0ull;
    const unsigned long long* fw = (const unsigned long long*)g_w1p;

    for (int c0 = 0; c0 < 512; c0 += 32) {
        __syncthreads();
        #pragma unroll
        for (int j = 0; j < 4; j++) {
            int idx = tid + j*256;
            int pt = idx >> 3, kq = idx & 7;
            float4 v = *(const float4*)&g_fused[(size_t)(pbase + pt)*512 + c0 + kq*4];
            fs[kq*4+0][pt] = v.x; fs[kq*4+1][pt] = v.y;
            fs[kq*4+2][pt] = v.z; fs[kq*4+3][pt] = v.w;
        }
        __syncthreads();
        #pragma unroll
        for (int kk = 0; kk < 32; kk++) {
            float4 aa = *(const float4*)&fs[kk][ty*8];
            float4 ab = *(const float4*)&fs[kk][ty*8 + 4];
            const ulonglong2* wp2 =
                (const ulonglong2*)(fw + (size_t)(c0+kk)*512 + ob*64 + tx*4);
            ulonglong2 w01 = wp2[0];
            ulonglong2 w23 = wp2[1];
            float av0 = aa.x, av1 = aa.y, av2 = aa.z, av3 = aa.w;
            float av4 = ab.x, av5 = ab.y, av6 = ab.z, av7 = ab.w;
            unsigned long long ad;
            #define DOPI(pi, a) \
                ad = pack2(a, a); \
                fma2(acc[pi][0], ad, w01.x); fma2(acc[pi][1], ad, w01.y); \
                fma2(acc[pi][2], ad, w23.x); fma2(acc[pi][3], ad, w23.y);
            DOPI(0, av0) DOPI(1, av1) DOPI(2, av2) DOPI(3, av3)
            DOPI(4, av4) DOPI(5, av5) DOPI(6, av6) DOPI(7, av7)
            #undef DOPI
        }
    }
    float so[8], qo[8];
    #pragma unroll
    for (int j = 0; j < 8; j++) { so[j] = 0.f; qo[j] = 0.f; }
    #pragma unroll
    for (int pi = 0; pi < 8; pi++) {
        float y[8];
        #pragma unroll
        for (int j = 0; j < 4; j++) unpack2(y[2*j], y[2*j+1], acc[pi][j]);
        int prow = pbase + ty*8 + pi;
        float4* dst = (float4*)&out[(size_t)prow*1024 + ob*128 + tx*8];
        dst[0] = make_float4(y[0], y[1], y[2], y[3]);
        dst[1] = make_float4(y[4], y[5], y[6], y[7]);
        #pragma unroll
        for (int j = 0; j < 8; j++) { so[j] += y[j]; qo[j] += y[j]*y[j]; }
    }
    #pragma unroll
    for (int j = 0; j < 8; j++) {
        sred[0][ty][tx*8 + j] = so[j];
        sred[1][ty][tx*8 + j] = qo[j];
    }
    __syncthreads();
    if (tid < 128) {
        float s = 0.f, q = 0.f;
        #pragma unroll
        for (int t = 0; t < 16; t++) { s += sred[0][t][tid]; q += sred[1][t][tid]; }
        g_psum[(size_t)(ob*128 + tid)*64 + pb] = s;
        g_pssq[(size_t)(ob*128 + tid)*64 + pb] = q;
    }
}

// ---------------- final BN + LeakyReLU in place --------------------------------
__global__ void normout_kernel(float* __restrict__ out) {
    int i = blockIdx.x*256 + threadIdx.x;
    if (i >= NP*1024) return;
    int o = i & 1023;
    float v = out[i] * g_scale[o] + g_shift[o];
    out[i] = v > 0.f ? v : 0.2f*v;
}

// ------------------------------- launcher -------------------------------------
extern "C" void kernel_launch(void* const* d_in, const int* in_sizes, int n_in,
                              void* d_out, int out_size) {
    (void)in_sizes; (void)n_in; (void)out_size;
    const float* x  = (const float*)d_in[0];
    const float* W[4]  = {(const float*)d_in[1],  (const float*)d_in[4],
                          (const float*)d_in[7],  (const float*)d_in[10]};
    const float* ga[4] = {(const float*)d_in[2],  (const float*)d_in[5],
                          (const float*)d_in[8],  (const float*)d_in[11]};
    const float* bt[4] = {(const float*)d_in[3],  (const float*)d_in[6],
                          (const float*)d_in[9],  (const float*)d_in[12]};
    const float* Wf = (const float*)d_in[13];
    const float* gf = (const float*)d_in[14];
    const float* bf = (const float*)d_in[15];
    float* out = (float*)d_out;

    float *h1, *h2;
    cudaGetSymbolAddress((void**)&h1, g_h1);
    cudaGetSymbolAddress((void**)&h2, g_h2);
    float* hn[2] = {h1, h2};

    const int Cs[4]    = {3, 64, 64, 128};
    const int Cps[4]   = {4, 64, 64, 128};
    const int lcs[4]   = {2, 6, 6, 7};
    const int OUTs[4]  = {64, 64, 128, 256};
    const int foffs[4] = {0, 64, 128, 256};

    xx_kernel<<<NP, 64>>>(x, 3);

    const float* hcur = x;
    for (int i = 0; i < 4; i++) {
        int C = Cs[i], Cp = Cps[i], OUT = OUTs[i];
        negdist_kernel<<<dim3(NN/64, NN/64, BB), 256>>>(hcur, C);
        topk_kernel<<<NP/8, 256>>>();
        int wtot = (Cp/4)*OUT;
        wtrans_kernel<<<(wtot + 255)/256, 256>>>(W[i], C, Cp, OUT);
        size_t smem = (size_t)(Cp + KK*Cp) * sizeof(float);
        edgeconv_kernel<<<NP, OUT/2, smem>>>(hcur, C, Cp, lcs[i], OUT, foffs[i]);
        chanstats_kernel<<<OUT, 256>>>(ga[i], bt[i], NP, 1.f/((float)NP*KK));
        normedge_kernel<<<NP, OUT>>>(OUT, foffs[i], hn[i & 1], (i < 3) ? 1 : 0);
        hcur = hn[i & 1];
    }

    wftrans_kernel<<<(262144 + 255)/256, 256>>>(Wf);
    final_kernel<<<dim3(64, 8), 256>>>(out);
    chanstats_kernel<<<1024, 256>>>(gf, bf, 64, 1.f/(float)NP);
    normout_kernel<<<(NP*1024 + 255)/256, 256>>>(out);
}

// round 5
// speedup vs baseline: 2.1043x; 1.1652x over previous
#include <cuda_runtime.h>
#include <cuda_bf16.h>
#include <cstdint>

#define BB 8
#define NN 1024
#define NP (BB*NN)
#define KK 20

// ---------------- scratch (device globals; no allocation allowed) -------------
__device__ float g_h1[NP*256];
__device__ float g_h2[NP*256];
__device__ float g_dist[(size_t)BB*NN*NN];
__device__ int   g_idx[NP*KK];
__device__ float g_xx[NP];
__device__ ulonglong2 g_w1p[131072];         // packed edge weights
__device__ float4     g_wdp[8192];           // packed (W2-W1)
__device__ float g_fused[(size_t)NP*512];
__device__ float g_psum[(size_t)NP*256];     // transposed: [o*P + p]
__device__ float g_pssq[(size_t)NP*256];
__device__ float g_scale[1024];
__device__ float g_shift[1024];
__device__ __nv_bfloat16 g_bh[1024*512];     // Wf split hi
__device__ __nv_bfloat16 g_bl[1024*512];     // Wf split lo

__device__ __forceinline__ void fma2(unsigned long long& d,
                                     unsigned long long a, unsigned long long b) {
    asm("fma.rn.f32x2 %0, %1, %2, %0;" : "+l"(d) : "l"(a), "l"(b));
}
__device__ __forceinline__ unsigned long long pack2(float lo, float hi) {
    unsigned long long r;
    asm("mov.b64 %0, {%1, %2};" : "=l"(r) : "f"(lo), "f"(hi));
    return r;
}
__device__ __forceinline__ void unpack2(float& lo, float& hi, unsigned long long v) {
    asm("mov.b64 {%0, %1}, %2;" : "=f"(lo), "=f"(hi) : "l"(v));
}
__device__ __forceinline__ uint32_t packbf2(float a, float b) {
    __nv_bfloat162 p;
    p.x = __float2bfloat16(a);
    p.y = __float2bfloat16(b);
    return *(uint32_t*)&p;
}
// HMMA m16n8k16 bf16 -> fp32 accumulate
__device__ __forceinline__ void mma16816(float* c, const uint32_t* a, const uint32_t* b) {
    asm volatile("mma.sync.aligned.m16n8k16.row.col.f32.bf16.bf16.f32 "
        "{%0,%1,%2,%3}, {%4,%5,%6,%7}, {%8,%9}, {%0,%1,%2,%3};"
        : "+f"(c[0]), "+f"(c[1]), "+f"(c[2]), "+f"(c[3])
        : "r"(a[0]), "r"(a[1]), "r"(a[2]), "r"(a[3]), "r"(b[0]), "r"(b[1]));
}

// ---------------- ||x||^2 per point (input layer only) -------------------------
__global__ void xx_kernel(const float* __restrict__ h, int C) {
    int p = blockIdx.x;
    __shared__ float sh[64];
    float s = 0.f;
    for (int c = threadIdx.x; c < C; c += 64) {
        float v = h[(size_t)p*C + c];
        s += v*v;
    }
    sh[threadIdx.x] = s; __syncthreads();
    for (int st = 32; st > 0; st >>= 1) {
        if (threadIdx.x < st) sh[threadIdx.x] += sh[threadIdx.x + st];
        __syncthreads();
    }
    if (threadIdx.x == 0) g_xx[p] = sh[0];
}

// ---------------- neg_dist: 64x64 register-tiled GEMM + f32x2 ------------------
__global__ void __launch_bounds__(256) negdist_kernel(const float* __restrict__ h, int C) {
    __shared__ float As[16][68];
    __shared__ float Bs[16][68];
    int b  = blockIdx.z;
    int n0 = blockIdx.y * 64, m0 = blockIdx.x * 64;
    int tid = threadIdx.x;
    int tx = tid & 15, ty = tid >> 4;
    unsigned long long acc[4][2];
    #pragma unroll
    for (int i = 0; i < 4; i++) { acc[i][0] = 0ull; acc[i][1] = 0ull; }

    for (int c0 = 0; c0 < C; c0 += 16) {
        #pragma unroll
        for (int r = 0; r < 4; r++) {
            int idx = tid + r*256;
            int cc = idx & 15, n = idx >> 4;
            int c = c0 + cc;
            As[cc][n] = (c < C) ? h[((size_t)(b*NN) + n0 + n)*C + c] : 0.f;
            Bs[cc][n] = (c < C) ? h[((size_t)(b*NN) + m0 + n)*C + c] : 0.f;
        }
        __syncthreads();
        #pragma unroll
        for (int kk = 0; kk < 16; kk++) {
            float4 a = *(const float4*)&As[kk][ty*4];
            ulonglong2 bb = *(const ulonglong2*)&Bs[kk][tx*4];
            unsigned long long a0 = pack2(a.x, a.x);
            unsigned long long a1 = pack2(a.y, a.y);
            unsigned long long a2 = pack2(a.z, a.z);
            unsigned long long a3 = pack2(a.w, a.w);
            fma2(acc[0][0], a0, bb.x); fma2(acc[0][1], a0, bb.y);
            fma2(acc[1][0], a1, bb.x); fma2(acc[1][1], a1, bb.y);
            fma2(acc[2][0], a2, bb.x); fma2(acc[2][1], a2, bb.y);
            fma2(acc[3][0], a3, bb.x); fma2(acc[3][1], a3, bb.y);
        }
        __syncthreads();
    }
    #pragma unroll
    for (int i = 0; i < 4; i++) {
        int n = n0 + ty*4 + i;
        float xn = g_xx[b*NN + n];
        #pragma unroll
        for (int jp = 0; jp < 2; jp++) {
            float lo, hi;
            unpack2(lo, hi, acc[i][jp]);
            int m = m0 + tx*4 + jp*2;
            g_dist[((size_t)(b*NN) + n)*NN + m]     = 2.f*lo - xn - g_xx[b*NN + m];
            g_dist[((size_t)(b*NN) + n)*NN + m + 1] = 2.f*hi - xn - g_xx[b*NN + m + 1];
        }
    }
}

// ---------------- top-k: warp per point, register-resident --------------------
__global__ void topk_kernel() {
    int lane = threadIdx.x & 31;
    int p = blockIdx.x * 8 + (threadIdx.x >> 5);
    const float* row = g_dist + (size_t)p*NN;
    float v[32];
    #pragma unroll
    for (int j = 0; j < 32; j++) v[j] = row[j*32 + lane];
    float lm = -1e30f; int ls = 0;
    #pragma unroll
    for (int j = 0; j < 32; j++) {
        if (v[j] > lm) { lm = v[j]; ls = j; }
    }
    for (int k = 0; k < KK; k++) {
        float bv = lm; int gi = ls*32 + lane;
        #pragma unroll
        for (int off = 16; off > 0; off >>= 1) {
            float ov = __shfl_xor_sync(0xffffffffu, bv, off);
            int   og = __shfl_xor_sync(0xffffffffu, gi, off);
            if (ov > bv || (ov == bv && og < gi)) { bv = ov; gi = og; }
        }
        if (lane == 0) g_idx[p*KK + k] = gi;
        if (lane == (gi & 31)) {
            int bs = gi >> 5;
            float nm = -1e30f; int ns = 0;
            #pragma unroll
            for (int j = 0; j < 32; j++) {
                if (j == bs) v[j] = -1e30f;
                if (v[j] > nm) { nm = v[j]; ns = j; }
            }
            lm = nm; ls = ns;
        }
    }
}

// ---------------- weight transform: W(out,2C) -> packed pairs -----------------
__global__ void wtrans_kernel(const float* __restrict__ W, int C, int Cp, int OUT) {
    int i = blockIdx.x*256 + threadIdx.x;
    int total = (Cp >> 2) * OUT;
    if (i >= total) return;
    int o = i % OUT;
    int c4 = i / OUT;
    float w1[4], wd[4];
    #pragma unroll
    for (int j = 0; j < 4; j++) {
        int c = c4*4 + j;
        if (c < C) {
            float a = W[(size_t)o*2*C + c];
            float b2 = W[(size_t)o*2*C + C + c];
            w1[j] = a; wd[j] = b2 - a;
        } else { w1[j] = 0.f; wd[j] = 0.f; }
    }
    ulonglong2 wp;
    wp.x = pack2(w1[0], w1[1]);
    wp.y = pack2(w1[2], w1[3]);
    g_w1p[i] = wp;
    g_wdp[i] = make_float4(wd[0], wd[1], wd[2], wd[3]);
}

// ---------------- edge conv: 2 outputs/thread, k-chunked, f32x2 ----------------
__global__ void edgeconv_kernel(const float* __restrict__ h, int C, int Cp,
                                int lc, int OUT, int foff) {
    extern __shared__ float sm[];
    float* ctr  = sm;
    float* feat = sm + Cp;
    __shared__ int nb[32];
    int p   = blockIdx.x;
    int tid = threadIdx.x;
    int HALF = blockDim.x;
    int b   = p >> 10;
    if (tid < KK) nb[tid] = g_idx[p*KK + tid];
    for (int c = tid; c < Cp; c += HALF)
        ctr[c] = (c < C) ? h[(size_t)p*C + c] : 0.f;
    __syncthreads();
    int mask = Cp - 1;
    for (int t = tid; t < KK*Cp; t += HALF) {
        int k = t >> lc, c = t & mask;
        feat[t] = (c < C) ? h[((size_t)((b << 10) + nb[k]))*C + c] : 0.f;
    }
    __syncthreads();

    int o0 = tid, o1 = tid + HALF;
    int C4 = Cp >> 2;
    const float4* c4p = (const float4*)ctr;
    float base0 = 0.f, base1 = 0.f;
    for (int c4 = 0; c4 < C4; c4++) {
        float4 cv = c4p[c4];
        float4 w0 = g_wdp[c4*OUT + o0];
        float4 w1 = g_wdp[c4*OUT + o1];
        base0 += w0.x*cv.x + w0.y*cv.y + w0.z*cv.z + w0.w*cv.w;
        base1 += w1.x*cv.x + w1.y*cv.y + w1.z*cv.z + w1.w*cv.w;
    }
    const ulonglong2* f2 = (const ulonglong2*)feat;
    float mx0=-1e30f, s0=0.f, q0=0.f;
    float mx1=-1e30f, s1=0.f, q1=0.f;
    #pragma unroll
    for (int kc = 0; kc < KK; kc += 10) {
        unsigned long long a0[10], a1[10];
        #pragma unroll
        for (int k = 0; k < 10; k++) { a0[k] = 0ull; a1[k] = 0ull; }
        for (int c4 = 0; c4 < C4; c4++) {
            ulonglong2 w0 = g_w1p[c4*OUT + o0];
            ulonglong2 w1 = g_w1p[c4*OUT + o1];
            #pragma unroll
            for (int k = 0; k < 10; k++) {
                ulonglong2 fv = f2[(kc+k)*C4 + c4];
                fma2(a0[k], w0.x, fv.x); fma2(a0[k], w0.y, fv.y);
                fma2(a1[k], w1.x, fv.x); fma2(a1[k], w1.y, fv.y);
            }
        }
        #pragma unroll
        for (int k = 0; k < 10; k++) {
            float lo, hi;
            unpack2(lo, hi, a0[k]);
            float y = base0 + lo + hi;
            mx0 = fmaxf(mx0, y); s0 += y; q0 += y*y;
            unpack2(lo, hi, a1[k]);
            y = base1 + lo + hi;
            mx1 = fmaxf(mx1, y); s1 += y; q1 += y*y;
        }
    }
    g_fused[(size_t)p*512 + foff + o0] = mx0;
    g_fused[(size_t)p*512 + foff + o1] = mx1;
    g_psum[(size_t)o0*NP + p] = s0; g_pssq[(size_t)o0*NP + p] = q0;
    g_psum[(size_t)o1*NP + p] = s1; g_pssq[(size_t)o1*NP + p] = q1;
}

// ---------------- per-channel BN stats (coalesced, deterministic) -------------
__global__ void chanstats_kernel(const float* __restrict__ g,
                                 const float* __restrict__ bta,
                                 int P, float invM) {
    int o = blockIdx.x;
    __shared__ float ssum[256], ssq[256];
    const float* ps = g_psum + (size_t)o*P;
    const float* pq = g_pssq + (size_t)o*P;
    float s = 0.f, q = 0.f;
    for (int i = threadIdx.x; i < P; i += 256) { s += ps[i]; q += pq[i]; }
    ssum[threadIdx.x] = s; ssq[threadIdx.x] = q;
    __syncthreads();
    for (int st = 128; st > 0; st >>= 1) {
        if (threadIdx.x < st) {
            ssum[threadIdx.x] += ssum[threadIdx.x + st];
            ssq [threadIdx.x] += ssq [threadIdx.x + st];
        }
        __syncthreads();
    }
    if (threadIdx.x == 0) {
        float mean = ssum[0] * invM;
        float var  = ssq[0] * invM - mean*mean;
        float sc   = rsqrtf(var + 1e-5f) * g[o];
        g_scale[o] = sc;
        g_shift[o] = bta[o] - mean * sc;
    }
}

// ---------------- BN + LeakyReLU on maxed values; also emits next ||h||^2 -----
__global__ void normedge_kernel(int OUT, int foff, float* __restrict__ hnext,
                                int wantxx) {
    __shared__ float sh[256];
    int p = blockIdx.x, o = threadIdx.x;
    float v = g_fused[(size_t)p*512 + foff + o] * g_scale[o] + g_shift[o];
    v = v > 0.f ? v : 0.2f*v;
    g_fused[(size_t)p*512 + foff + o] = v;
    hnext[(size_t)p*OUT + o] = v;
    sh[o] = v*v;
    __syncthreads();
    for (int st = OUT >> 1; st > 0; st >>= 1) {
        if (o < st) sh[o] += sh[o + st];
        __syncthreads();
    }
    if (o == 0 && wantxx) g_xx[p] = sh[0];
}

// ---------------- split Wf into bf16 hi/lo -------------------------------------
__global__ void wfsplit_kernel(const float* __restrict__ Wf) {
    int i = blockIdx.x*256 + threadIdx.x;
    if (i >= 1024*512) return;
    float w = Wf[i];
    __nv_bfloat16 h = __float2bfloat16(w);
    float r = w - __bfloat162float(h);
    g_bh[i] = h;
    g_bl[i] = __float2bfloat16(r);
}

// ---------------- final linear via HMMA bf16-split ----------------------------
// grid (64, 8); block 256 = 8 warps (2 m x 4 n). Block tile 128x128, K chunk 32.
__global__ void __launch_bounds__(256) finalmma_kernel(float* __restrict__ out) {
    __shared__ uint32_t sAh[128*18], sAl[128*18];   // [row][pair] stride 18 u32
    __shared__ uint32_t sBh[128*18], sBl[128*18];
    __shared__ float red[2][2][128];

    int tid = threadIdx.x, wid = tid >> 5, lane = tid & 31;
    int g = lane >> 2, t = lane & 3;
    int wm = wid >> 2, wn = wid & 3;
    int pb = blockIdx.x, ob = blockIdx.y;
    int pbase = pb * 128, obase = ob * 128;

    float acc[4][4][4];
    #pragma unroll
    for (int mi = 0; mi < 4; mi++)
        #pragma unroll
        for (int ni = 0; ni < 4; ni++)
            #pragma unroll
            for (int j = 0; j < 4; j++) acc[mi][ni][j] = 0.f;

    const uint32_t* bh2 = (const uint32_t*)g_bh;
    const uint32_t* bl2 = (const uint32_t*)g_bl;

    for (int c0 = 0; c0 < 512; c0 += 32) {
        __syncthreads();
        #pragma unroll
        for (int i = tid; i < 2048; i += 256) {
            int row = i >> 4, kp = i & 15;
            float2 v = *(const float2*)&g_fused[(size_t)(pbase + row)*512 + c0 + kp*2];
            __nv_bfloat16 h0 = __float2bfloat16(v.x);
            __nv_bfloat16 h1 = __float2bfloat16(v.y);
            float r0 = v.x - __bfloat162float(h0);
            float r1 = v.y - __bfloat162float(h1);
            __nv_bfloat162 hp; hp.x = h0; hp.y = h1;
            sAh[row*18 + kp] = *(uint32_t*)&hp;
            sAl[row*18 + kp] = packbf2(r0, r1);
            size_t gi = (size_t)(obase + row)*256 + (c0 >> 1) + kp;
            sBh[row*18 + kp] = bh2[gi];
            sBl[row*18 + kp] = bl2[gi];
        }
        __syncthreads();
        #pragma unroll
        for (int ks = 0; ks < 2; ks++) {
            int kp0 = ks * 8;
            uint32_t ah[4][4], al[4][4];
            #pragma unroll
            for (int mi = 0; mi < 4; mi++) {
                int r = wm*64 + mi*16 + g;
                ah[mi][0] = sAh[r*18 + kp0 + t];
                ah[mi][1] = sAh[(r+8)*18 + kp0 + t];
                ah[mi][2] = sAh[r*18 + kp0 + 4 + t];
                ah[mi][3] = sAh[(r+8)*18 + kp0 + 4 + t];
                al[mi][0] = sAl[r*18 + kp0 + t];
                al[mi][1] = sAl[(r+8)*18 + kp0 + t];
                al[mi][2] = sAl[r*18 + kp0 + 4 + t];
                al[mi][3] = sAl[(r+8)*18 + kp0 + 4 + t];
            }
            uint32_t bh[4][2], bl[4][2];
            #pragma unroll
            for (int ni = 0; ni < 4; ni++) {
                int n = wn*32 + ni*8 + g;
                bh[ni][0] = sBh[n*18 + kp0 + t];
                bh[ni][1] = sBh[n*18 + kp0 + 4 + t];
                bl[ni][0] = sBl[n*18 + kp0 + t];
                bl[ni][1] = sBl[n*18 + kp0 + 4 + t];
            }
            #pragma unroll
            for (int mi = 0; mi < 4; mi++)
                #pragma unroll
                for (int ni = 0; ni < 4; ni++) {
                    mma16816(acc[mi][ni], ah[mi], bh[ni]);
                    mma16816(acc[mi][ni], ah[mi], bl[ni]);
                    mma16816(acc[mi][ni], al[mi], bh[ni]);
                }
        }
    }

    // epilogue: raw y + per-column BN partials (deterministic)
    #pragma unroll
    for (int ni = 0; ni < 4; ni++) {
        float s0 = 0.f, s1 = 0.f, q0 = 0.f, q1 = 0.f;
        #pragma unroll
        for (int mi = 0; mi < 4; mi++) {
            float* a = acc[mi][ni];
            int row = pbase + wm*64 + mi*16 + g;
            int col = obase + wn*32 + ni*8 + t*2;
            *(float2*)&out[(size_t)row*1024 + col]     = make_float2(a[0], a[1]);
            *(float2*)&out[(size_t)(row+8)*1024 + col] = make_float2(a[2], a[3]);
            s0 += a[0] + a[2]; s1 += a[1] + a[3];
            q0 += a[0]*a[0] + a[2]*a[2];
            q1 += a[1]*a[1] + a[3]*a[3];
        }
        #pragma unroll
        for (int off = 4; off < 32; off <<= 1) {
            s0 += __shfl_xor_sync(0xffffffffu, s0, off);
            s1 += __shfl_xor_sync(0xffffffffu, s1, off);
            q0 += __shfl_xor_sync(0xffffffffu, q0, off);
            q1 += __shfl_xor_sync(0xffffffffu, q1, off);
        }
        if (g == 0) {
            int colw = wn*32 + ni*8 + t*2;
            red[wm][0][colw]   = s0;
            red[wm][0][colw+1] = s1;
            red[wm][1][colw]   = q0;
            red[wm][1][colw+1] = q1;
        }
    }
    __syncthreads();
    if (tid < 128) {
        float s = red[0][0][tid] + red[1][0][tid];
        float q = red[0][1][tid] + red[1][1][tid];
        g_psum[(size_t)(obase + tid)*64 + pb] = s;
        g_pssq[(size_t)(obase + tid)*64 + pb] = q;
    }
}

// ---------------- final BN + LeakyReLU in place --------------------------------
__global__ void normout_kernel(float* __restrict__ out) {
    int i = blockIdx.x*256 + threadIdx.x;
    if (i >= NP*1024) return;
    int o = i & 1023;
    float v = out[i] * g_scale[o] + g_shift[o];
    out[i] = v > 0.f ? v : 0.2f*v;
}

// ------------------------------- launcher -------------------------------------
extern "C" void kernel_launch(void* const* d_in, const int* in_sizes, int n_in,
                              void* d_out, int out_size) {
    (void)in_sizes; (void)n_in; (void)out_size;
    const float* x  = (const float*)d_in[0];
    const float* W[4]  = {(const float*)d_in[1],  (const float*)d_in[4],
                          (const float*)d_in[7],  (const float*)d_in[10]};
    const float* ga[4] = {(const float*)d_in[2],  (const float*)d_in[5],
                          (const float*)d_in[8],  (const float*)d_in[11]};
    const float* bt[4] = {(const float*)d_in[3],  (const float*)d_in[6],
                          (const float*)d_in[9],  (const float*)d_in[12]};
    const float* Wf = (const float*)d_in[13];
    const float* gf = (const float*)d_in[14];
    const float* bf = (const float*)d_in[15];
    float* out = (float*)d_out;

    float *h1, *h2;
    cudaGetSymbolAddress((void**)&h1, g_h1);
    cudaGetSymbolAddress((void**)&h2, g_h2);
    float* hn[2] = {h1, h2};

    const int Cs[4]    = {3, 64, 64, 128};
    const int Cps[4]   = {4, 64, 64, 128};
    const int lcs[4]   = {2, 6, 6, 7};
    const int OUTs[4]  = {64, 64, 128, 256};
    const int foffs[4] = {0, 64, 128, 256};

    wfsplit_kernel<<<(1024*512 + 255)/256, 256>>>(Wf);
    xx_kernel<<<NP, 64>>>(x, 3);

    const float* hcur = x;
    for (int i = 0; i < 4; i++) {
        int C = Cs[i], Cp = Cps[i], OUT = OUTs[i];
        negdist_kernel<<<dim3(NN/64, NN/64, BB), 256>>>(hcur, C);
        topk_kernel<<<NP/8, 256>>>();
        int wtot = (Cp/4)*OUT;
        wtrans_kernel<<<(wtot + 255)/256, 256>>>(W[i], C, Cp, OUT);
        size_t smem = (size_t)(Cp + KK*Cp) * sizeof(float);
        edgeconv_kernel<<<NP, OUT/2, smem>>>(hcur, C, Cp, lcs[i], OUT, foffs[i]);
        chanstats_kernel<<<OUT, 256>>>(ga[i], bt[i], NP, 1.f/((float)NP*KK));
        normedge_kernel<<<NP, OUT>>>(OUT, foffs[i], hn[i & 1], (i < 3) ? 1 : 0);
        hcur = hn[i & 1];
    }

    finalmma_kernel<<<dim3(64, 8), 256>>>(out);
    chanstats_kernel<<<1024, 256>>>(gf, bf, 64, 1.f/(float)NP);
    normout_kernel<<<(NP*1024 + 255)/256, 256>>>(out);
}